// round 15
// baseline (speedup 1.0000x reference)
#include <cuda_runtime.h>
#include <cuda_bf16.h>
#include <cstdint>

#define B_ 8
#define N_ 2048
#define D_ 128
#define ALPHA 0.2f
#define KT 32
#define NT (N_ / KT)        // 64 j-tiles
#define ROWS 32             // rows per k3 CTA

// k3 smem layout (bytes); P/B tiles XOR-swizzled, 64B rows
#define OFF_WH1   0
#define OFF_SINV  128
#define OFF_RED   256
#define OFF_WH2   512                        // 8KB
#define OFF_MASK  (512 + 8192)               // 8704: 8KB (32 rows x 64 words)
#define OFF_P     17408                      // 2 x 2048
#define OFF_B     21504                      // 2 x 8192
#define K3_SMEM   37888
#define P_BUF_BYTES 2048
#define B_BUF_BYTES 8192

#define CP_ASYNC16(dst, src) \
    asm volatile("cp.async.cg.shared.global [%0], [%1], 16;" :: "r"(dst), "l"(src))
#define CP_COMMIT() asm volatile("cp.async.commit_group;" ::: "memory")
#define CP_WAIT0()  asm volatile("cp.async.wait_group 0;" ::: "memory")

// ---------------- scratch (device globals; no allocations allowed) ----------
__device__ __align__(16) float g_Wh1[B_ * N_];
__device__ __align__(16) float g_Wh2[B_ * N_];
__device__ __align__(16) __nv_bfloat16 g_WhT[(size_t)B_ * D_ * N_]; // [b][d][n] bf16, 4MB

// ========== K1: Wh = h @ W (fp32 register-tiled) + Wh1/Wh2 + bf16 WhT ======
__global__ void __launch_bounds__(256) k1_wh(const float* __restrict__ h,
                                             const float* __restrict__ W,
                                             const float* __restrict__ a) {
    __shared__ __align__(16) float s_hT[32][68];
    __shared__ __align__(16) float s_W[32][128];
    __shared__ float s_red1[64 * 33];
    __shared__ float s_red2[64 * 33];

    int tid = threadIdx.x;
    int tx = tid & 31, ty = tid >> 5;
    int rowbase = blockIdx.x * 64;

    float a1v[4], a2v[4];
#pragma unroll
    for (int j = 0; j < 4; j++) {
        a1v[j] = a[tx * 4 + j];
        a2v[j] = a[D_ + tx * 4 + j];
    }

    float acc[8][4];
#pragma unroll
    for (int i = 0; i < 8; i++)
#pragma unroll
        for (int j = 0; j < 4; j++) acc[i][j] = 0.f;

    for (int kc = 0; kc < 4; kc++) {
#pragma unroll
        for (int z = 0; z < 4; z++) {
            int idx = tid + z * 256;
            int kr = idx >> 5, c4 = idx & 31;
            *(float4*)&s_W[kr][c4 * 4] =
                *(const float4*)(W + (size_t)(kc * 32 + kr) * D_ + c4 * 4);
        }
#pragma unroll
        for (int z = 0; z < 2; z++) {
            int idx = tid + z * 256;
            int row = idx >> 3, k4 = (idx & 7) * 4;
            float4 v = *(const float4*)(h + (size_t)(rowbase + row) * D_ + kc * 32 + k4);
            s_hT[k4 + 0][row] = v.x;
            s_hT[k4 + 1][row] = v.y;
            s_hT[k4 + 2][row] = v.z;
            s_hT[k4 + 3][row] = v.w;
        }
        __syncthreads();
#pragma unroll 8
        for (int k = 0; k < 32; k++) {
            float4 h0 = *(float4*)&s_hT[k][ty * 8];
            float4 h1 = *(float4*)&s_hT[k][ty * 8 + 4];
            float4 w0 = *(float4*)&s_W[k][tx * 4];
            float hr[8] = {h0.x, h0.y, h0.z, h0.w, h1.x, h1.y, h1.z, h1.w};
            float wc_[4] = {w0.x, w0.y, w0.z, w0.w};
#pragma unroll
            for (int i = 0; i < 8; i++)
#pragma unroll
                for (int j = 0; j < 4; j++) acc[i][j] = fmaf(hr[i], wc_[j], acc[i][j]);
        }
        __syncthreads();
    }

#pragma unroll
    for (int i = 0; i < 8; i++) {
        float p1 = acc[i][0] * a1v[0] + acc[i][1] * a1v[1] +
                   acc[i][2] * a1v[2] + acc[i][3] * a1v[3];
        float p2 = acc[i][0] * a2v[0] + acc[i][1] * a2v[1] +
                   acc[i][2] * a2v[2] + acc[i][3] * a2v[3];
        s_red1[(ty * 8 + i) * 33 + tx] = p1;
        s_red2[(ty * 8 + i) * 33 + tx] = p2;
    }
    __syncthreads();
    if (tid < 64) {
        float s1 = 0.f, s2 = 0.f;
#pragma unroll
        for (int x = 0; x < 32; x++) {
            s1 += s_red1[tid * 33 + x];
            s2 += s_red2[tid * 33 + x];
        }
        g_Wh1[rowbase + tid] = s1;
        g_Wh2[rowbase + tid] = s2;
    }

    int b = rowbase >> 11;
    int n0 = rowbase & (N_ - 1);
#pragma unroll
    for (int j = 0; j < 4; j++) {
        int col = tx * 4 + j;
        uint32_t pk[4];
#pragma unroll
        for (int i = 0; i < 4; i++) {
            __nv_bfloat162 v = __floats2bfloat162_rn(acc[2 * i][j], acc[2 * i + 1][j]);
            pk[i] = *reinterpret_cast<uint32_t*>(&v);
        }
        *(uint4*)(g_WhT + ((size_t)(b * D_ + col)) * N_ + n0 + ty * 8) =
            make_uint4(pk[0], pk[1], pk[2], pk[3]);
    }
}

// =============== K3: fused rowsum+mask + attention + warp-MMA + residual ===
// grid (64, 8), 128 threads (4 warps), 32 rows/CTA, KT=32, target 5 CTAs/SM.
__device__ __forceinline__ uint32_t packbf2(float x, float y) {
    __nv_bfloat162 v = __floats2bfloat162_rn(x, y);
    return *reinterpret_cast<uint32_t*>(&v);
}

__global__ void __launch_bounds__(128, 5) k3_attn(const int* __restrict__ adj,
                                                  const float* __restrict__ h,
                                                  float* __restrict__ out,
                                                  float* __restrict__ attn) {
    extern __shared__ char smem[];
    float* s_wh1 = (float*)(smem + OFF_WH1);
    float* s_Sinv = (float*)(smem + OFF_SINV);
    float* s_red = (float*)(smem + OFF_RED);
    float* s_wh2 = (float*)(smem + OFF_WH2);
    uint32_t* s_mask = (uint32_t*)(smem + OFF_MASK);   // [32][64] words

    int tid = threadIdx.x;
    int lane = tid & 31;
    int wid = tid >> 5;        // 0..3
    int b = blockIdx.y;
    int n0 = blockIdx.x * ROWS;

    const float* wh2b = g_Wh2 + b * N_;
    const __nv_bfloat16* whTb = g_WhT + (size_t)b * D_ * N_;

    // ---- stage wh2 (2048 floats) + wh1 (32) ----
    {
        float4* d4 = (float4*)s_wh2;
        const float4* s4 = (const float4*)wh2b;
        d4[tid] = s4[tid];
        d4[tid + 128] = s4[tid + 128];
        d4[tid + 256] = s4[tid + 256];
        d4[tid + 384] = s4[tid + 384];
    }
    if (tid < ROWS) s_wh1[tid] = g_Wh1[b * N_ + n0 + tid];
    __syncthreads();

    // ---- pass 1: row sums + bitmask; warp owns 8 rows ----
    {
        int row0 = wid * 8;
#pragma unroll
        for (int i = 0; i < 8; i++) {
            int row = row0 + i;
            float wh1 = s_wh1[row];
            const int4* a4 = (const int4*)(adj + (size_t)(b * N_ + n0 + row) * N_);
            const float4* w4 = (const float4*)s_wh2;
            float s = 0.f;
            uint32_t* mrow = s_mask + row * 64;
#pragma unroll 4
            for (int jt = 0; jt < 16; jt++) {
                int j = jt * 32 + lane;
                int4 m = a4[j];
                float4 v = w4[j];
                float e;
                e = wh1 + v.x; e = fmaxf(e, ALPHA * e); if (m.x) s += __expf(e);
                e = wh1 + v.y; e = fmaxf(e, ALPHA * e); if (m.y) s += __expf(e);
                e = wh1 + v.z; e = fmaxf(e, ALPHA * e); if (m.z) s += __expf(e);
                e = wh1 + v.w; e = fmaxf(e, ALPHA * e); if (m.w) s += __expf(e);
                uint32_t nib = (m.x ? 1u : 0u) | (m.y ? 2u : 0u) |
                               (m.z ? 4u : 0u) | (m.w ? 8u : 0u);
                uint32_t v32 = nib << ((lane & 7) * 4);
                v32 |= __shfl_xor_sync(0xffffffffu, v32, 1);
                v32 |= __shfl_xor_sync(0xffffffffu, v32, 2);
                v32 |= __shfl_xor_sync(0xffffffffu, v32, 4);
                if ((lane & 7) == 0) mrow[jt * 4 + (lane >> 3)] = v32;
            }
#pragma unroll
            for (int o = 16; o > 0; o >>= 1) s += __shfl_xor_sync(0xffffffffu, s, o);
            if (lane == 0) s_red[row] = s;
        }
        __syncthreads();
        if (tid < ROWS) s_Sinv[tid] = 1.f / s_red[tid];
        __syncthreads();
    }

    // ---- role constants ----
    int wr = wid & 1;            // row group (16 rows)
    int wc = wid >> 1;           // col half (64 cols)
    // A fragment: base offset for kk=0; kk toggles bit 5.
    int a_row = wr * 16 + (lane & 7) + ((lane >> 3) & 1) * 8;
    uint32_t a_off0 = (uint32_t)(a_row * 64 +
        (((lane >> 4) * 16) ^ (((a_row >> 1) & 3) << 4)));
    // B fragments: 4 groups of 16 n-rows.
    uint32_t b_off0[4];
#pragma unroll
    for (int g = 0; g < 4; g++) {
        int d = wc * 64 + g * 16 + ((lane >> 4) & 1) * 8 + (lane & 7);
        b_off0[g] = (uint32_t)(d * 64 +
            ((((lane >> 3) & 1) * 16) ^ (((d >> 1) & 3) << 4)));
    }

    uint32_t sP0 = (uint32_t)__cvta_generic_to_shared(smem + OFF_P);
    uint32_t sB0 = (uint32_t)__cvta_generic_to_shared(smem + OFF_B);

    float acc[8][4];
#pragma unroll
    for (int i = 0; i < 8; i++) { acc[i][0] = acc[i][1] = acc[i][2] = acc[i][3] = 0.f; }

    // ---- P-compute mapping: lane = (cl 0-7: 4 cols) x (rg 0-3); rows rg, rg+4
    int prow = wid * 8;
    int cl = lane & 7;
    int rg = lane >> 3;
    int row_a = prow + rg, row_b = prow + rg + 4;
    float wh1r[2] = {s_wh1[row_a], s_wh1[row_b]};
    float sir[2] = {s_Sinv[row_a], s_Sinv[row_b]};
    float* attp0 = attn + (size_t)(b * N_ + n0 + row_a) * N_ + cl * 4;
    float* attp1 = attn + (size_t)(b * N_ + n0 + row_b) * N_ + cl * 4;
    uint32_t poff_a = (uint32_t)(row_a * 64 + ((cl * 8) ^ (((row_a >> 1) & 3) << 4)));
    uint32_t poff_b = (uint32_t)(row_b * 64 + ((cl * 8) ^ (((row_b >> 1) & 3) << 4)));
    int mshift = cl * 4;

    // B cp.async: 4 chunks/thread; chunk z = base + z*(32 rows) — fixed strides
    int row0b = tid >> 2, ch0 = tid & 3;
    const char* bsrc0 = (const char*)(whTb + (size_t)row0b * N_) + ch0 * 16;
    uint32_t bdst0 = (uint32_t)(row0b * 64 + ((ch0 * 16) ^ (((row0b >> 1) & 3) << 4)));

    uint32_t pk[4];

#define COMPUTE_P(T)                                                             \
    {                                                                            \
        float4 w4 = *(const float4*)(s_wh2 + (T) * KT + cl * 4);                 \
        uint32_t ba = s_mask[row_a * 64 + (T)] >> mshift;                        \
        uint32_t bb = s_mask[row_b * 64 + (T)] >> mshift;                        \
        float e0, e1, e2, e3, p0, p1, p2, p3;                                    \
        e0 = wh1r[0] + w4.x; e0 = fmaxf(e0, ALPHA * e0);                         \
        e1 = wh1r[0] + w4.y; e1 = fmaxf(e1, ALPHA * e1);                         \
        e2 = wh1r[0] + w4.z; e2 = fmaxf(e2, ALPHA * e2);                         \
        e3 = wh1r[0] + w4.w; e3 = fmaxf(e3, ALPHA * e3);                         \
        p0 = (ba & 1u) ? __expf(e0) * sir[0] : 0.f;                              \
        p1 = (ba & 2u) ? __expf(e1) * sir[0] : 0.f;                              \
        p2 = (ba & 4u) ? __expf(e2) * sir[0] : 0.f;                              \
        p3 = (ba & 8u) ? __expf(e3) * sir[0] : 0.f;                              \
        *(float4*)(attp0 + (size_t)(T) * KT) = make_float4(p0, p1, p2, p3);      \
        pk[0] = packbf2(p0, p1); pk[1] = packbf2(p2, p3);                        \
        e0 = wh1r[1] + w4.x; e0 = fmaxf(e0, ALPHA * e0);                         \
        e1 = wh1r[1] + w4.y; e1 = fmaxf(e1, ALPHA * e1);                         \
        e2 = wh1r[1] + w4.z; e2 = fmaxf(e2, ALPHA * e2);                         \
        e3 = wh1r[1] + w4.w; e3 = fmaxf(e3, ALPHA * e3);                         \
        p0 = (bb & 1u) ? __expf(e0) * sir[1] : 0.f;                              \
        p1 = (bb & 2u) ? __expf(e1) * sir[1] : 0.f;                              \
        p2 = (bb & 4u) ? __expf(e2) * sir[1] : 0.f;                              \
        p3 = (bb & 8u) ? __expf(e3) * sir[1] : 0.f;                              \
        *(float4*)(attp1 + (size_t)(T) * KT) = make_float4(p0, p1, p2, p3);      \
        pk[2] = packbf2(p0, p1); pk[3] = packbf2(p2, p3);                        \
    }

    // prologue: B(0) in flight, P(0) in registers
#pragma unroll
    for (int z = 0; z < 4; z++)
        CP_ASYNC16(sB0 + bdst0 + z * 2048, bsrc0 + (size_t)z * 131072);
    CP_COMMIT();
    COMPUTE_P(0);

    // ---- pass 2 (pipelined) ----
#pragma unroll 1
    for (int t = 0; t < NT; t++) {
        uint32_t sP = sP0 + (t & 1) * P_BUF_BYTES;
        uint32_t sB = sB0 + (t & 1) * B_BUF_BYTES;

        CP_WAIT0();   // B(t) landed
        asm volatile("st.shared.v2.b32 [%0], {%1,%2};" ::
                     "r"(sP + poff_a), "r"(pk[0]), "r"(pk[1]));
        asm volatile("st.shared.v2.b32 [%0], {%1,%2};" ::
                     "r"(sP + poff_b), "r"(pk[2]), "r"(pk[3]));
        __syncthreads();  // B(t), P(t) visible; all warps past MMA(t-1)

        if (t + 1 < NT) {
            uint32_t sBn = sB0 + ((t + 1) & 1) * B_BUF_BYTES;
            size_t so = (size_t)(t + 1) * (KT * 2);
#pragma unroll
            for (int z = 0; z < 4; z++)
                CP_ASYNC16(sBn + bdst0 + z * 2048, bsrc0 + (size_t)z * 131072 + so);
            CP_COMMIT();
            COMPUTE_P(t + 1);
        }

        // MMA(t): 2 k-steps
#pragma unroll
        for (int kk = 0; kk < 2; kk++) {
            uint32_t A0, A1, A2, A3;
            {
                uint32_t sa = sP + (a_off0 ^ (kk << 5));
                asm volatile("ldmatrix.sync.aligned.m8n8.x4.shared.b16 {%0,%1,%2,%3}, [%4];\n"
                             : "=r"(A0), "=r"(A1), "=r"(A2), "=r"(A3) : "r"(sa));
            }
#pragma unroll
            for (int g = 0; g < 4; g++) {
                uint32_t B0, B1, B2, B3;
                uint32_t sb = sB + (b_off0[g] ^ (kk << 5));
                asm volatile("ldmatrix.sync.aligned.m8n8.x4.shared.b16 {%0,%1,%2,%3}, [%4];\n"
                             : "=r"(B0), "=r"(B1), "=r"(B2), "=r"(B3) : "r"(sb));
                int nb = g * 2;
                asm volatile("mma.sync.aligned.m16n8k16.row.col.f32.bf16.bf16.f32 "
                             "{%0,%1,%2,%3}, {%4,%5,%6,%7}, {%8,%9}, {%0,%1,%2,%3};\n"
                             : "+f"(acc[nb][0]), "+f"(acc[nb][1]), "+f"(acc[nb][2]), "+f"(acc[nb][3])
                             : "r"(A0), "r"(A1), "r"(A2), "r"(A3), "r"(B0), "r"(B1));
                asm volatile("mma.sync.aligned.m16n8k16.row.col.f32.bf16.bf16.f32 "
                             "{%0,%1,%2,%3}, {%4,%5,%6,%7}, {%8,%9}, {%0,%1,%2,%3};\n"
                             : "+f"(acc[nb + 1][0]), "+f"(acc[nb + 1][1]),
                               "+f"(acc[nb + 1][2]), "+f"(acc[nb + 1][3])
                             : "r"(A0), "r"(A1), "r"(A2), "r"(A3), "r"(B2), "r"(B3));
            }
        }
    }

    // ---- epilogue: out = h + h_prime ----
    {
        int row_lo = n0 + wr * 16 + (lane >> 2);
        int gr_lo = b * N_ + row_lo;
        int gr_hi = gr_lo + 8;
        const float* hlo = h + (size_t)gr_lo * D_;
        const float* hhi = h + (size_t)gr_hi * D_;
        float* olo = out + (size_t)gr_lo * D_;
        float* ohi = out + (size_t)gr_hi * D_;
#pragma unroll
        for (int nb = 0; nb < 8; nb++) {
            int c = wc * 64 + nb * 8 + (lane & 3) * 2;
            float2 hv0 = *(const float2*)(hlo + c);
            float2 hv1 = *(const float2*)(hhi + c);
            *(float2*)(olo + c) = make_float2(hv0.x + acc[nb][0], hv0.y + acc[nb][1]);
            *(float2*)(ohi + c) = make_float2(hv1.x + acc[nb][2], hv1.y + acc[nb][3]);
        }
    }
}

// ---------------------------------------------------------------------------
extern "C" void kernel_launch(void* const* d_in, const int* in_sizes, int n_in,
                              void* d_out, int out_size) {
    const float* h   = (const float*)d_in[0];
    const int*   adj = (const int*)d_in[1];
    const float* W   = (const float*)d_in[2];
    const float* a   = (const float*)d_in[3];
    float* out  = (float*)d_out;
    float* attn = out + (size_t)B_ * N_ * D_;

    k1_wh<<<(B_ * N_) / 64, 256>>>(h, W, a);
    k3_attn<<<dim3(N_ / ROWS, B_), 128, K3_SMEM>>>(adj, h, out, attn);
}

// round 16
// speedup vs baseline: 1.1581x; 1.1581x over previous
#include <cuda_runtime.h>
#include <cuda_bf16.h>
#include <cstdint>

#define B_ 8
#define N_ 2048
#define D_ 128
#define ALPHA 0.2f
#define KT 32
#define NT (N_ / KT)        // 64 j-tiles
#define ROWS 16             // rows per k3 CTA

// k3 smem layout (bytes); P/B tiles XOR-swizzled, 64B rows
#define OFF_WH1   0
#define OFF_SINV  64
#define OFF_RED   128
#define OFF_WH2   256                        // 8KB
#define OFF_MASK  (256 + 8192)               // 8448: 4KB (16 rows x 64 words)
#define OFF_P     12544                      // 2 x 1024
#define OFF_B     14592                      // 2 x 8192
#define K3_SMEM   30976
#define P_BUF_BYTES 1024
#define B_BUF_BYTES 8192

#define CP_ASYNC16(dst, src) \
    asm volatile("cp.async.cg.shared.global [%0], [%1], 16;" :: "r"(dst), "l"(src))
#define CP_COMMIT() asm volatile("cp.async.commit_group;" ::: "memory")
#define CP_WAIT0()  asm volatile("cp.async.wait_group 0;" ::: "memory")

// ---------------- scratch (device globals; no allocations allowed) ----------
__device__ __align__(16) float g_Wh1[B_ * N_];
__device__ __align__(16) float g_Wh2[B_ * N_];
__device__ __align__(16) __nv_bfloat16 g_WhT[(size_t)B_ * D_ * N_]; // [b][d][n] bf16, 4MB

// ========== K1: Wh = h @ W (fp32 register-tiled) + Wh1/Wh2 + bf16 WhT ======
__global__ void __launch_bounds__(256) k1_wh(const float* __restrict__ h,
                                             const float* __restrict__ W,
                                             const float* __restrict__ a) {
    __shared__ __align__(16) float s_hT[32][68];
    __shared__ __align__(16) float s_W[32][128];
    __shared__ float s_red1[64 * 33];
    __shared__ float s_red2[64 * 33];

    int tid = threadIdx.x;
    int tx = tid & 31, ty = tid >> 5;
    int rowbase = blockIdx.x * 64;

    float a1v[4], a2v[4];
#pragma unroll
    for (int j = 0; j < 4; j++) {
        a1v[j] = a[tx * 4 + j];
        a2v[j] = a[D_ + tx * 4 + j];
    }

    float acc[8][4];
#pragma unroll
    for (int i = 0; i < 8; i++)
#pragma unroll
        for (int j = 0; j < 4; j++) acc[i][j] = 0.f;

    for (int kc = 0; kc < 4; kc++) {
#pragma unroll
        for (int z = 0; z < 4; z++) {
            int idx = tid + z * 256;
            int kr = idx >> 5, c4 = idx & 31;
            *(float4*)&s_W[kr][c4 * 4] =
                *(const float4*)(W + (size_t)(kc * 32 + kr) * D_ + c4 * 4);
        }
#pragma unroll
        for (int z = 0; z < 2; z++) {
            int idx = tid + z * 256;
            int row = idx >> 3, k4 = (idx & 7) * 4;
            float4 v = *(const float4*)(h + (size_t)(rowbase + row) * D_ + kc * 32 + k4);
            s_hT[k4 + 0][row] = v.x;
            s_hT[k4 + 1][row] = v.y;
            s_hT[k4 + 2][row] = v.z;
            s_hT[k4 + 3][row] = v.w;
        }
        __syncthreads();
#pragma unroll 8
        for (int k = 0; k < 32; k++) {
            float4 h0 = *(float4*)&s_hT[k][ty * 8];
            float4 h1 = *(float4*)&s_hT[k][ty * 8 + 4];
            float4 w0 = *(float4*)&s_W[k][tx * 4];
            float hr[8] = {h0.x, h0.y, h0.z, h0.w, h1.x, h1.y, h1.z, h1.w};
            float wc_[4] = {w0.x, w0.y, w0.z, w0.w};
#pragma unroll
            for (int i = 0; i < 8; i++)
#pragma unroll
                for (int j = 0; j < 4; j++) acc[i][j] = fmaf(hr[i], wc_[j], acc[i][j]);
        }
        __syncthreads();
    }

#pragma unroll
    for (int i = 0; i < 8; i++) {
        float p1 = acc[i][0] * a1v[0] + acc[i][1] * a1v[1] +
                   acc[i][2] * a1v[2] + acc[i][3] * a1v[3];
        float p2 = acc[i][0] * a2v[0] + acc[i][1] * a2v[1] +
                   acc[i][2] * a2v[2] + acc[i][3] * a2v[3];
        s_red1[(ty * 8 + i) * 33 + tx] = p1;
        s_red2[(ty * 8 + i) * 33 + tx] = p2;
    }
    __syncthreads();
    if (tid < 64) {
        float s1 = 0.f, s2 = 0.f;
#pragma unroll
        for (int x = 0; x < 32; x++) {
            s1 += s_red1[tid * 33 + x];
            s2 += s_red2[tid * 33 + x];
        }
        g_Wh1[rowbase + tid] = s1;
        g_Wh2[rowbase + tid] = s2;
    }

    int b = rowbase >> 11;
    int n0 = rowbase & (N_ - 1);
#pragma unroll
    for (int j = 0; j < 4; j++) {
        int col = tx * 4 + j;
        uint32_t pk[4];
#pragma unroll
        for (int i = 0; i < 4; i++) {
            __nv_bfloat162 v = __floats2bfloat162_rn(acc[2 * i][j], acc[2 * i + 1][j]);
            pk[i] = *reinterpret_cast<uint32_t*>(&v);
        }
        *(uint4*)(g_WhT + ((size_t)(b * D_ + col)) * N_ + n0 + ty * 8) =
            make_uint4(pk[0], pk[1], pk[2], pk[3]);
    }
}

// =============== K3: fused rowsum+mask + attention + warp-MMA + residual ===
// grid (128, 8), 128 threads (4 warps), 16 rows/CTA -> 4096 warps total.
// Warp w: P-compute rows w*4..+4 (1 row x 4 cols per lane); MMA cols w*32..+32.
__device__ __forceinline__ uint32_t packbf2(float x, float y) {
    __nv_bfloat162 v = __floats2bfloat162_rn(x, y);
    return *reinterpret_cast<uint32_t*>(&v);
}

__global__ void __launch_bounds__(128, 6) k3_attn(const int* __restrict__ adj,
                                                  const float* __restrict__ h,
                                                  float* __restrict__ out,
                                                  float* __restrict__ attn) {
    extern __shared__ char smem[];
    float* s_wh1 = (float*)(smem + OFF_WH1);
    float* s_Sinv = (float*)(smem + OFF_SINV);
    float* s_red = (float*)(smem + OFF_RED);
    float* s_wh2 = (float*)(smem + OFF_WH2);
    uint32_t* s_mask = (uint32_t*)(smem + OFF_MASK);   // [16][64] words

    int tid = threadIdx.x;
    int lane = tid & 31;
    int wid = tid >> 5;        // 0..3
    int b = blockIdx.y;
    int n0 = blockIdx.x * ROWS;

    const float* wh2b = g_Wh2 + b * N_;
    const __nv_bfloat16* whTb = g_WhT + (size_t)b * D_ * N_;

    // ---- stage wh2 (2048 floats) + wh1 (16) ----
    {
        float4* d4 = (float4*)s_wh2;
        const float4* s4 = (const float4*)wh2b;
        d4[tid] = s4[tid];
        d4[tid + 128] = s4[tid + 128];
        d4[tid + 256] = s4[tid + 256];
        d4[tid + 384] = s4[tid + 384];
    }
    if (tid < ROWS) s_wh1[tid] = g_Wh1[b * N_ + n0 + tid];
    __syncthreads();

    // ---- pass 1: row sums + bitmask; warp owns 4 rows ----
    {
        int row0 = wid * 4;
#pragma unroll
        for (int i = 0; i < 4; i++) {
            int row = row0 + i;
            float wh1 = s_wh1[row];
            const int4* a4 = (const int4*)(adj + (size_t)(b * N_ + n0 + row) * N_);
            const float4* w4 = (const float4*)s_wh2;
            float s = 0.f;
            uint32_t* mrow = s_mask + row * 64;
#pragma unroll 4
            for (int jt = 0; jt < 16; jt++) {
                int j = jt * 32 + lane;
                int4 m = a4[j];
                float4 v = w4[j];
                float e;
                e = wh1 + v.x; e = fmaxf(e, ALPHA * e); if (m.x) s += __expf(e);
                e = wh1 + v.y; e = fmaxf(e, ALPHA * e); if (m.y) s += __expf(e);
                e = wh1 + v.z; e = fmaxf(e, ALPHA * e); if (m.z) s += __expf(e);
                e = wh1 + v.w; e = fmaxf(e, ALPHA * e); if (m.w) s += __expf(e);
                uint32_t nib = (m.x ? 1u : 0u) | (m.y ? 2u : 0u) |
                               (m.z ? 4u : 0u) | (m.w ? 8u : 0u);
                uint32_t v32 = nib << ((lane & 7) * 4);
                v32 |= __shfl_xor_sync(0xffffffffu, v32, 1);
                v32 |= __shfl_xor_sync(0xffffffffu, v32, 2);
                v32 |= __shfl_xor_sync(0xffffffffu, v32, 4);
                if ((lane & 7) == 0) mrow[jt * 4 + (lane >> 3)] = v32;
            }
#pragma unroll
            for (int o = 16; o > 0; o >>= 1) s += __shfl_xor_sync(0xffffffffu, s, o);
            if (lane == 0) s_red[row] = s;
        }
        __syncthreads();
        if (tid < ROWS) s_Sinv[tid] = 1.f / s_red[tid];
        __syncthreads();
    }

    // ---- role constants ----
    // A fragment (16 rows, shared by all warps); kk toggles bit 5.
    int a_row = (lane & 7) + ((lane >> 3) & 1) * 8;
    uint32_t a_off0 = (uint32_t)(a_row * 64 +
        (((lane >> 4) * 16) ^ (((a_row >> 1) & 3) << 4)));
    // B fragments: warp wid covers d-cols [wid*32, +32) -> 2 groups of 16.
    uint32_t b_off0[2];
#pragma unroll
    for (int g = 0; g < 2; g++) {
        int d = wid * 32 + g * 16 + ((lane >> 4) & 1) * 8 + (lane & 7);
        b_off0[g] = (uint32_t)(d * 64 +
            ((((lane >> 3) & 1) * 16) ^ (((d >> 1) & 3) << 4)));
    }

    uint32_t sP0 = (uint32_t)__cvta_generic_to_shared(smem + OFF_P);
    uint32_t sB0 = (uint32_t)__cvta_generic_to_shared(smem + OFF_B);

    float acc[4][4];
#pragma unroll
    for (int i = 0; i < 4; i++) { acc[i][0] = acc[i][1] = acc[i][2] = acc[i][3] = 0.f; }

    // ---- P-compute mapping: lane = (rg 0-3: row) x (cl 0-7: 4 cols) ----
    int cl = lane & 7;
    int rg = lane >> 3;
    int prow = wid * 4 + rg;       // the one row this lane owns
    float wh1r = s_wh1[prow];
    float sir = s_Sinv[prow];
    float* attp = attn + (size_t)(b * N_ + n0 + prow) * N_ + cl * 4;
    uint32_t poff = (uint32_t)(prow * 64 + ((cl * 8) ^ (((prow >> 1) & 3) << 4)));
    int mshift = cl * 4;
    const uint32_t* mrow = s_mask + prow * 64;

    // B cp.async: 4 chunks/thread (128 d-rows x 64B per buffer)
    int row0b = tid >> 2, ch0 = tid & 3;
    const char* bsrc0 = (const char*)(whTb + (size_t)row0b * N_) + ch0 * 16;
    uint32_t bdst0 = (uint32_t)(row0b * 64 + ((ch0 * 16) ^ (((row0b >> 1) & 3) << 4)));

    uint32_t pk[2];

#define COMPUTE_P(T)                                                             \
    {                                                                            \
        float4 w4 = *(const float4*)(s_wh2 + (T) * KT + cl * 4);                 \
        uint32_t ba = mrow[(T)] >> mshift;                                       \
        float e0, e1, e2, e3, p0, p1, p2, p3;                                    \
        e0 = wh1r + w4.x; e0 = fmaxf(e0, ALPHA * e0);                            \
        e1 = wh1r + w4.y; e1 = fmaxf(e1, ALPHA * e1);                            \
        e2 = wh1r + w4.z; e2 = fmaxf(e2, ALPHA * e2);                            \
        e3 = wh1r + w4.w; e3 = fmaxf(e3, ALPHA * e3);                            \
        p0 = (ba & 1u) ? __expf(e0) * sir : 0.f;                                 \
        p1 = (ba & 2u) ? __expf(e1) * sir : 0.f;                                 \
        p2 = (ba & 4u) ? __expf(e2) * sir : 0.f;                                 \
        p3 = (ba & 8u) ? __expf(e3) * sir : 0.f;                                 \
        *(float4*)(attp + (size_t)(T) * KT) = make_float4(p0, p1, p2, p3);       \
        pk[0] = packbf2(p0, p1); pk[1] = packbf2(p2, p3);                        \
    }

    // prologue: B(0) in flight, P(0) in registers
#pragma unroll
    for (int z = 0; z < 4; z++)
        CP_ASYNC16(sB0 + bdst0 + z * 2048, bsrc0 + (size_t)z * 131072);
    CP_COMMIT();
    COMPUTE_P(0);

    // ---- pass 2 (pipelined) ----
#pragma unroll 1
    for (int t = 0; t < NT; t++) {
        uint32_t sP = sP0 + (t & 1) * P_BUF_BYTES;
        uint32_t sB = sB0 + (t & 1) * B_BUF_BYTES;

        CP_WAIT0();   // B(t) landed
        asm volatile("st.shared.v2.b32 [%0], {%1,%2};" ::
                     "r"(sP + poff), "r"(pk[0]), "r"(pk[1]));
        __syncthreads();  // B(t), P(t) visible; all warps past MMA(t-1)

        if (t + 1 < NT) {
            uint32_t sBn = sB0 + ((t + 1) & 1) * B_BUF_BYTES;
            size_t so = (size_t)(t + 1) * (KT * 2);
#pragma unroll
            for (int z = 0; z < 4; z++)
                CP_ASYNC16(sBn + bdst0 + z * 2048, bsrc0 + (size_t)z * 131072 + so);
            CP_COMMIT();
            COMPUTE_P(t + 1);
        }

        // MMA(t): 2 k-steps, 2 n-groups
#pragma unroll
        for (int kk = 0; kk < 2; kk++) {
            uint32_t A0, A1, A2, A3;
            {
                uint32_t sa = sP + (a_off0 ^ (kk << 5));
                asm volatile("ldmatrix.sync.aligned.m8n8.x4.shared.b16 {%0,%1,%2,%3}, [%4];\n"
                             : "=r"(A0), "=r"(A1), "=r"(A2), "=r"(A3) : "r"(sa));
            }
#pragma unroll
            for (int g = 0; g < 2; g++) {
                uint32_t B0, B1, B2, B3;
                uint32_t sb = sB + (b_off0[g] ^ (kk << 5));
                asm volatile("ldmatrix.sync.aligned.m8n8.x4.shared.b16 {%0,%1,%2,%3}, [%4];\n"
                             : "=r"(B0), "=r"(B1), "=r"(B2), "=r"(B3) : "r"(sb));
                int nb = g * 2;
                asm volatile("mma.sync.aligned.m16n8k16.row.col.f32.bf16.bf16.f32 "
                             "{%0,%1,%2,%3}, {%4,%5,%6,%7}, {%8,%9}, {%0,%1,%2,%3};\n"
                             : "+f"(acc[nb][0]), "+f"(acc[nb][1]), "+f"(acc[nb][2]), "+f"(acc[nb][3])
                             : "r"(A0), "r"(A1), "r"(A2), "r"(A3), "r"(B0), "r"(B1));
                asm volatile("mma.sync.aligned.m16n8k16.row.col.f32.bf16.bf16.f32 "
                             "{%0,%1,%2,%3}, {%4,%5,%6,%7}, {%8,%9}, {%0,%1,%2,%3};\n"
                             : "+f"(acc[nb + 1][0]), "+f"(acc[nb + 1][1]),
                               "+f"(acc[nb + 1][2]), "+f"(acc[nb + 1][3])
                             : "r"(A0), "r"(A1), "r"(A2), "r"(A3), "r"(B2), "r"(B3));
            }
        }
    }

    // ---- epilogue: out = h + h_prime ----
    {
        int row_lo = n0 + (lane >> 2);
        int gr_lo = b * N_ + row_lo;
        int gr_hi = gr_lo + 8;
        const float* hlo = h + (size_t)gr_lo * D_;
        const float* hhi = h + (size_t)gr_hi * D_;
        float* olo = out + (size_t)gr_lo * D_;
        float* ohi = out + (size_t)gr_hi * D_;
#pragma unroll
        for (int nb = 0; nb < 4; nb++) {
            int c = wid * 32 + nb * 8 + (lane & 3) * 2;
            float2 hv0 = *(const float2*)(hlo + c);
            float2 hv1 = *(const float2*)(hhi + c);
            *(float2*)(olo + c) = make_float2(hv0.x + acc[nb][0], hv0.y + acc[nb][1]);
            *(float2*)(ohi + c) = make_float2(hv1.x + acc[nb][2], hv1.y + acc[nb][3]);
        }
    }
}

// ---------------------------------------------------------------------------
extern "C" void kernel_launch(void* const* d_in, const int* in_sizes, int n_in,
                              void* d_out, int out_size) {
    const float* h   = (const float*)d_in[0];
    const int*   adj = (const int*)d_in[1];
    const float* W   = (const float*)d_in[2];
    const float* a   = (const float*)d_in[3];
    float* out  = (float*)d_out;
    float* attn = out + (size_t)B_ * N_ * D_;

    k1_wh<<<(B_ * N_) / 64, 256>>>(h, W, a);
    k3_attn<<<dim3(N_ / ROWS, B_), 128, K3_SMEM>>>(adj, h, out, attn);
}